// round 10
// baseline (speedup 1.0000x reference)
#include <cuda_runtime.h>
#include <cuda_fp16.h>
#include <cstdint>

#define T_DIM   64
#define IN_DIM  4100
#define OUT_DIM 12288
#define G_DIM   820
#define GPAD    824
#define KP      6592          // GPAD * 8
#define NCHUNK  103           // KP / 64
#define O_TILE  64
#define NCTA    192           // OUT_DIM / O_TILE
#define LDSW    72            // smem row stride in halves (conflict-free)

#define N_X   (T_DIM * IN_DIM)        // 262400
#define N_IDX (OUT_DIM * G_DIM * 2)   // 20152320
#define N_CB  2560
#define N_SC  (OUT_DIM)               // 12288

__device__ unsigned g_xmax_bits, g_m16_bits, g_mb16_bits, g_m32_bits;
__device__ int   g_interp;    // 0=f16, 1=bf16, 2=f32
__device__ float g_cbm, g_xm;
__device__ __align__(16) uint4  g_cb4[512];                  // normalized, padded codebook
__device__ __align__(16) __half g_xpad[T_DIM * KP];
__device__ __align__(16) __half g_W[(size_t)OUT_DIM * KP];   // dequantized weights (162 MB)

static __device__ __forceinline__ uint32_t hadd2u(uint32_t a, uint32_t b) {
    __half2 ha = *reinterpret_cast<__half2*>(&a);
    __half2 hb = *reinterpret_cast<__half2*>(&b);
    __half2 r  = __hadd2(ha, hb);
    return *reinterpret_cast<uint32_t*>(&r);
}
static __device__ __forceinline__ float f16v(unsigned short u) {
    return __half2float(__ushort_as_half(u));
}
static __device__ __forceinline__ float bf16v(unsigned short u) {
    return __uint_as_float(((unsigned)u) << 16);
}
static __device__ __forceinline__ float finite_or_zero(float v) {
    unsigned u = __float_as_uint(v);
    return ((u & 0x7f800000u) == 0x7f800000u) ? 0.f : v;
}

// ---------- kernel: reset ----------
__global__ void k_init() {
    g_xmax_bits = 0u; g_m16_bits = 0u; g_mb16_bits = 0u; g_m32_bits = 0u;
}

// ---------- kernel: abs-max scans (x; codebook under 3 interpretations) ----------
__global__ void k_scan(const float* __restrict__ x, const unsigned short* __restrict__ cb) {
    float mx = 0.f, mf = 0.f, mb = 0.f, m3 = 0.f;
    int stride = gridDim.x * blockDim.x;
    int t0 = blockIdx.x * blockDim.x + threadIdx.x;
    for (int i = t0; i < N_X; i += stride) mx = fmaxf(mx, fabsf(x[i]));
    for (int i = t0; i < N_CB; i += stride) {
        unsigned short u = cb[i];
        mf = fmaxf(mf, fabsf(f16v(u)));
        mb = fmaxf(mb, fabsf(bf16v(u)));
    }
    for (int i = t0; i < N_CB / 2; i += stride) {   // only first 5120 bytes: safe for 16-bit data
        unsigned lo = cb[2 * i], hi = cb[2 * i + 1];
        m3 = fmaxf(m3, fabsf(__uint_as_float(lo | (hi << 16))));
    }
#pragma unroll
    for (int o = 16; o; o >>= 1) {
        mx = fmaxf(mx, __shfl_xor_sync(0xffffffffu, mx, o));
        mf = fmaxf(mf, __shfl_xor_sync(0xffffffffu, mf, o));
        mb = fmaxf(mb, __shfl_xor_sync(0xffffffffu, mb, o));
        m3 = fmaxf(m3, __shfl_xor_sync(0xffffffffu, m3, o));
    }
    if ((threadIdx.x & 31) == 0) {
        atomicMax(&g_xmax_bits, __float_as_uint(mx));
        atomicMax(&g_m16_bits,  __float_as_uint(mf));
        atomicMax(&g_mb16_bits, __float_as_uint(mb));
        atomicMax(&g_m32_bits,  __float_as_uint(m3));
    }
}

// ---------- kernel: resolve dtype + scalars (1 warp) ----------
__global__ void k_resolve(const unsigned short* __restrict__ cb) {
    int lane = threadIdx.x;
    float mf = __uint_as_float(g_m16_bits);
    float mb = __uint_as_float(g_mb16_bits);
    float m3 = __uint_as_float(g_m32_bits);
    int interp; float cbm;
    // true codebook abs-max ~0.19; sanity window [0.02, 0.75]
    if      (mf >= 0.02f && mf <= 0.75f) { interp = 0; cbm = mf; }
    else if (mb >= 0.02f && mb <= 0.75f) { interp = 1; cbm = mb; }
    else if (m3 >= 0.02f && m3 <= 0.75f) { interp = 2; cbm = m3; }
    else                                  { interp = 1; cbm = mb; }
    if (interp == 2) {
        // full fp32 max (buffer confirmed 4B/elem -> safe to read all 2560 floats)
        const float* f = (const float*)cb;
        float m = 0.f;
        for (int i = lane; i < N_CB; i += 32) m = fmaxf(m, fabsf(f[i]));
#pragma unroll
        for (int o = 16; o; o >>= 1) m = fmaxf(m, __shfl_xor_sync(0xffffffffu, m, o));
        cbm = m;
    }
    if (lane == 0) {
        g_interp = interp;
        g_cbm = fmaxf(cbm, 1.0f);
        g_xm  = fmaxf(__uint_as_float(g_xmax_bits), 1.0f) * 8.0f;
    }
}

// ---------- kernel: build normalized padded codebook (512 entries x 8 halves) ----------
__global__ void k_cbprep(const unsigned short* __restrict__ cb) {
    int e = blockIdx.x * blockDim.x + threadIdx.x;
    if (e >= 512) return;
    int interp = g_interp;
    float cbm = g_cbm;
    union { uint4 v4; __half h[8]; } u;
#pragma unroll
    for (int j = 0; j < 8; ++j) {
        float v = 0.f;
        if (j < 5) {
            int k = e * 5 + j;
            if      (interp == 0) v = f16v(cb[k]);
            else if (interp == 1) v = bf16v(cb[k]);
            else                  v = ((const float*)cb)[k];
        }
        u.h[j] = __float2half(v / cbm);
    }
    g_cb4[e] = u.v4;
}

// ---------- kernel: build padded fp16 x [64][6592] ----------
__global__ void k_xpad(const float* __restrict__ x) {
    int idx = blockIdx.x * blockDim.x + threadIdx.x;
    if (idx >= T_DIM * KP) return;
    float xm = g_xm;
    int t = idx / KP;
    int k = idx - t * KP;
    int g = k >> 3, j = k & 7;
    __half v = __ushort_as_half((unsigned short)0);
    if (j < 5 && g < G_DIM)
        v = __float2half(x[t * IN_DIM + g * 5 + j] / xm);
    g_xpad[idx] = v;
}

// ---------- kernel: dequantize W (one CTA per output row) ----------
__global__ void __launch_bounds__(256) k_dequant(const int* __restrict__ indices) {
    __shared__ __align__(16) uint4 scb[512];
    int tid = threadIdx.x;
    scb[tid]       = g_cb4[tid];
    scb[tid + 256] = g_cb4[tid + 256];
    __syncthreads();

    int o = blockIdx.x;
    const int2* ip = reinterpret_cast<const int2*>(indices) + (size_t)o * G_DIM;
    __half* wrow = g_W + (size_t)o * KP;
    for (int g = tid; g < GPAD; g += 256) {
        uint4 w;
        if (g < G_DIM) {
            int2 id = ip[g];
            uint4 e0 = scb[id.x & 255];
            uint4 e1 = scb[256 + (id.y & 255)];
            w.x = hadd2u(e0.x, e1.x);
            w.y = hadd2u(e0.y, e1.y);
            w.z = hadd2u(e0.z, e1.z);
            w.w = hadd2u(e0.w, e1.w);
        } else {
            w = make_uint4(0, 0, 0, 0);
        }
        *reinterpret_cast<uint4*>(wrow + g * 8) = w;
    }
}

// ---------- kernel: GEMM 64 x 12288 x 6592, fp16 in / fp32 accum ----------
__global__ void __launch_bounds__(256, 2)
k_gemm(const float* __restrict__ scales, float* __restrict__ out) {
    __shared__ __align__(16) __half s_w[O_TILE][LDSW];
    __shared__ __align__(16) __half s_x[T_DIM][LDSW];

    const int tid  = threadIdx.x;
    const int lane = tid & 31;
    const int wid  = tid >> 5;
    const int o_base = blockIdx.x * O_TILE;
    const int r = tid >> 2;       // tile row this thread loads (0..63)
    const int q = tid & 3;        // 16-half segment

    const int m_base = (wid & 3) * 16;   // x rows for this warp
    const int n_base = (wid >> 2) * 32;  // w rows for this warp

    float acc[4][4];
#pragma unroll
    for (int nt = 0; nt < 4; ++nt)
#pragma unroll
        for (int c = 0; c < 4; ++c) acc[nt][c] = 0.f;

    for (int i = 0; i < NCHUNK; ++i) {
        const __half* wsrc = g_W + (size_t)(o_base + r) * KP + i * 64 + q * 16;
        *reinterpret_cast<uint4*>(&s_w[r][q * 16])     = *reinterpret_cast<const uint4*>(wsrc);
        *reinterpret_cast<uint4*>(&s_w[r][q * 16 + 8]) = *reinterpret_cast<const uint4*>(wsrc + 8);
        const __half* xsrc = g_xpad + (size_t)r * KP + i * 64 + q * 16;
        *reinterpret_cast<uint4*>(&s_x[r][q * 16])     = *reinterpret_cast<const uint4*>(xsrc);
        *reinterpret_cast<uint4*>(&s_x[r][q * 16 + 8]) = *reinterpret_cast<const uint4*>(xsrc + 8);
        __syncthreads();

#pragma unroll
        for (int kk = 0; kk < 4; ++kk) {
            // A fragment (m16n8k16.row.col), per PTX ISA tables:
            // a0:(m=lane/4,      k=(lane%4)*2)  a1:(m+8, k)  a2:(m, k+8)  a3:(m+8, k+8)
            const int ar = m_base + (lane >> 2);
            const int ac = kk * 16 + (lane & 3) * 2;
            uint32_t a0 = *reinterpret_cast<const uint32_t*>(&s_x[ar][ac]);
            uint32_t a1 = *reinterpret_cast<const uint32_t*>(&s_x[ar + 8][ac]);
            uint32_t a2 = *reinterpret_cast<const uint32_t*>(&s_x[ar][ac + 8]);
            uint32_t a3 = *reinterpret_cast<const uint32_t*>(&s_x[ar + 8][ac + 8]);
#pragma unroll
            for (int nt = 0; nt < 4; ++nt) {
                // B fragment: b0:(k=(lane%4)*2, n=lane/4)  b1:(k+8, n)
                const int br = n_base + nt * 8 + (lane >> 2);
                uint32_t b0 = *reinterpret_cast<const uint32_t*>(&s_w[br][ac]);
                uint32_t b1 = *reinterpret_cast<const uint32_t*>(&s_w[br][ac + 8]);
                asm volatile("mma.sync.aligned.m16n8k16.row.col.f32.f16.f16.f32 "
                             "{%0,%1,%2,%3}, {%4,%5,%6,%7}, {%8,%9}, {%0,%1,%2,%3};"
                             : "+f"(acc[nt][0]), "+f"(acc[nt][1]),
                               "+f"(acc[nt][2]), "+f"(acc[nt][3])
                             : "r"(a0), "r"(a1), "r"(a2), "r"(a3), "r"(b0), "r"(b1));
            }
        }
        __syncthreads();
    }

    // epilogue: C fragment c0:(m=lane/4, n=(lane%4)*2) c1:(m,n+1) c2:(m+8,n) c3:(m+8,n+1)
    const float fac = g_xm * g_cbm;
    const int t0 = m_base + (lane >> 2);
#pragma unroll
    for (int nt = 0; nt < 4; ++nt) {
        const int o = o_base + n_base + nt * 8 + (lane & 3) * 2;
        const float s0 = scales[o] * fac;
        const float s1 = scales[o + 1] * fac;
        float v0 = finite_or_zero(acc[nt][0] * s0);
        float v1 = finite_or_zero(acc[nt][1] * s1);
        float v2 = finite_or_zero(acc[nt][2] * s0);
        float v3 = finite_or_zero(acc[nt][3] * s1);
        *reinterpret_cast<float2*>(out + (size_t)t0 * OUT_DIM + o)       = make_float2(v0, v1);
        *reinterpret_cast<float2*>(out + (size_t)(t0 + 8) * OUT_DIM + o) = make_float2(v2, v3);
    }
}

extern "C" void kernel_launch(void* const* d_in, const int* in_sizes, int n_in,
                              void* d_out, int out_size) {
    // Bind by element count (all four distinct); positional fallback.
    const float* x = nullptr;
    const int* indices = nullptr;
    const unsigned short* cbooks = nullptr;
    const float* scales = nullptr;
    for (int i = 0; i < n_in; ++i) {
        switch (in_sizes[i]) {
            case N_X:   x       = (const float*)d_in[i];          break;
            case N_IDX: indices = (const int*)d_in[i];            break;
            case N_CB:  cbooks  = (const unsigned short*)d_in[i]; break;
            case N_SC:  scales  = (const float*)d_in[i];          break;
            default: break;
        }
    }
    if (!x)       x       = (const float*)d_in[0];
    if (!indices) indices = (const int*)d_in[1];
    if (!cbooks)  cbooks  = (const unsigned short*)d_in[2];
    if (!scales)  scales  = (const float*)d_in[3];
    float* out = (float*)d_out;

    k_init<<<1, 1>>>();
    k_scan<<<64, 256>>>(x, cbooks);
    k_resolve<<<1, 32>>>(cbooks);
    k_cbprep<<<2, 256>>>(cbooks);
    k_xpad<<<(T_DIM * KP + 255) / 256, 256>>>(x);
    k_dequant<<<OUT_DIM, 256>>>(indices);
    k_gemm<<<NCTA, 256>>>(scales, out);
}

// round 12
// speedup vs baseline: 1.8232x; 1.8232x over previous
#include <cuda_runtime.h>
#include <cuda_fp16.h>
#include <cstdint>

#define T_DIM   64
#define IN_DIM  4100
#define OUT_DIM 12288
#define G_DIM   820
#define KP      6592          // 824 groups * 8
#define NCHUNK  103           // KP / 64
#define O_TILE  128
#define NOTILE  96            // OUT_DIM / O_TILE
#define SPLITS  3
#define NCTA    (NOTILE * SPLITS)
#define LDSW    72            // smem row stride in halves (144B) -> conflict-free

#define N_X   (T_DIM * IN_DIM)        // 262400
#define N_IDX (OUT_DIM * G_DIM * 2)   // 20152320
#define N_CB  2560
#define N_SC  (OUT_DIM)               // 12288

__device__ unsigned g_xmax_bits, g_m16_bits, g_mb16_bits, g_m32_bits;
__device__ int   g_interp;    // 0=f16, 1=bf16, 2=f32
__device__ float g_cbm, g_xm;
__device__ __align__(16) __half g_xpad[T_DIM * KP];
__device__ __align__(16) float  g_part[SPLITS][(size_t)T_DIM * OUT_DIM];  // 9.4 MB

static __device__ __forceinline__ uint32_t hadd2u(uint32_t a, uint32_t b) {
    __half2 ha = *reinterpret_cast<__half2*>(&a);
    __half2 hb = *reinterpret_cast<__half2*>(&b);
    __half2 r  = __hadd2(ha, hb);
    return *reinterpret_cast<uint32_t*>(&r);
}
static __device__ __forceinline__ float f16v(unsigned short u) {
    return __half2float(__ushort_as_half(u));
}
static __device__ __forceinline__ float bf16v(unsigned short u) {
    return __uint_as_float(((unsigned)u) << 16);
}
static __device__ __forceinline__ float finite_or_zero(float v) {
    unsigned u = __float_as_uint(v);
    return ((u & 0x7f800000u) == 0x7f800000u) ? 0.f : v;
}

// ---------- kernel: reset ----------
__global__ void k_init() {
    g_xmax_bits = 0u; g_m16_bits = 0u; g_mb16_bits = 0u; g_m32_bits = 0u;
}

// ---------- kernel: abs-max scans (verified R5) ----------
__global__ void k_scan(const float* __restrict__ x, const unsigned short* __restrict__ cb) {
    float mx = 0.f, mf = 0.f, mb = 0.f, m3 = 0.f;
    int stride = gridDim.x * blockDim.x;
    int t0 = blockIdx.x * blockDim.x + threadIdx.x;
    for (int i = t0; i < N_X; i += stride) mx = fmaxf(mx, fabsf(x[i]));
    for (int i = t0; i < N_CB; i += stride) {
        unsigned short u = cb[i];
        mf = fmaxf(mf, fabsf(f16v(u)));
        mb = fmaxf(mb, fabsf(bf16v(u)));
    }
    for (int i = t0; i < N_CB / 2; i += stride) {   // safe for 16-bit data
        unsigned lo = cb[2 * i], hi = cb[2 * i + 1];
        m3 = fmaxf(m3, fabsf(__uint_as_float(lo | (hi << 16))));
    }
#pragma unroll
    for (int o = 16; o; o >>= 1) {
        mx = fmaxf(mx, __shfl_xor_sync(0xffffffffu, mx, o));
        mf = fmaxf(mf, __shfl_xor_sync(0xffffffffu, mf, o));
        mb = fmaxf(mb, __shfl_xor_sync(0xffffffffu, mb, o));
        m3 = fmaxf(m3, __shfl_xor_sync(0xffffffffu, m3, o));
    }
    if ((threadIdx.x & 31) == 0) {
        atomicMax(&g_xmax_bits, __float_as_uint(mx));
        atomicMax(&g_m16_bits,  __float_as_uint(mf));
        atomicMax(&g_mb16_bits, __float_as_uint(mb));
        atomicMax(&g_m32_bits,  __float_as_uint(m3));
    }
}

// ---------- kernel: resolve dtype + scalars (verified R5) ----------
__global__ void k_resolve(const unsigned short* __restrict__ cb) {
    int lane = threadIdx.x;
    float mf = __uint_as_float(g_m16_bits);
    float mb = __uint_as_float(g_mb16_bits);
    float m3 = __uint_as_float(g_m32_bits);
    int interp; float cbm;
    if      (mf >= 0.02f && mf <= 0.75f) { interp = 0; cbm = mf; }
    else if (mb >= 0.02f && mb <= 0.75f) { interp = 1; cbm = mb; }
    else if (m3 >= 0.02f && m3 <= 0.75f) { interp = 2; cbm = m3; }
    else                                  { interp = 1; cbm = mb; }
    if (interp == 2) {
        const float* f = (const float*)cb;
        float m = 0.f;
        for (int i = lane; i < N_CB; i += 32) m = fmaxf(m, fabsf(f[i]));
#pragma unroll
        for (int o = 16; o; o >>= 1) m = fmaxf(m, __shfl_xor_sync(0xffffffffu, m, o));
        cbm = m;
    }
    if (lane == 0) {
        g_interp = interp;
        g_cbm = fmaxf(cbm, 1.0f);
        g_xm  = fmaxf(__uint_as_float(g_xmax_bits), 1.0f) * 8.0f;
    }
}

// ---------- kernel: build padded fp16 x [64][6592] (verified R5) ----------
__global__ void k_xpad(const float* __restrict__ x) {
    int idx = blockIdx.x * blockDim.x + threadIdx.x;
    if (idx >= T_DIM * KP) return;
    float xm = g_xm;
    int t = idx / KP;
    int k = idx - t * KP;
    int g = k >> 3, j = k & 7;
    __half v = __ushort_as_half((unsigned short)0);
    if (j < 5 && g < G_DIM)
        v = __float2half(x[t * IN_DIM + g * 5 + j] / xm);
    g_xpad[idx] = v;
}

// ---------- fused dequant + GEMM ----------
__global__ void __launch_bounds__(256, 2)
k_fused(const int* __restrict__ indices, const unsigned short* __restrict__ cb) {
    __shared__ __align__(16) uint4  s_cb[512];            // 8 KB
    __shared__ __align__(16) __half s_w[O_TILE][LDSW];    // 18 KB
    __shared__ __align__(16) __half s_x[T_DIM][LDSW];     // 9 KB

    const int tid  = threadIdx.x;
    const int lane = tid & 31;
    const int wid  = tid >> 5;
    const int o_tile = blockIdx.x % NOTILE;
    const int split  = blockIdx.x / NOTILE;
    const int o_base = o_tile * O_TILE;
    const int c_lo = (split == 0) ? 0  : (split == 1 ? 35 : 69);
    const int c_hi = (split == 0) ? 35 : (split == 1 ? 69 : 103);

    // ---- build normalized padded codebook in smem (from verified R5 cbprep) ----
    {
        const int interp = g_interp;
        const float cbm = g_cbm;
        for (int e = tid; e < 512; e += 256) {
            union { uint4 v4; __half h[8]; } u;
#pragma unroll
            for (int j = 0; j < 8; ++j) {
                float v = 0.f;
                if (j < 5) {
                    int k = e * 5 + j;
                    if      (interp == 0) v = f16v(cb[k]);
                    else if (interp == 1) v = bf16v(cb[k]);
                    else                  v = ((const float*)cb)[k];
                }
                u.h[j] = __float2half(v / cbm);
            }
            s_cb[e] = u.v4;
        }
    }
    __syncthreads();

    // ---- dequant / staging assignments ----
    const int dq_row = tid >> 1;            // 0..127: W tile row
    const int dq_g   = (tid & 1) * 4;       // group segment within chunk (0 or 4)
    const int4* ibase = (const int4*)indices + (size_t)(o_base + dq_row) * (G_DIM / 2);
    const int xr = tid >> 2;                // 0..63: x tile row
    const int xs = tid & 3;                 // 16-half segment
    const uint4* xp = (const uint4*)(g_xpad + (size_t)xr * KP);

    // warp tiling: m32 x n32 per warp (Wm=2, Wn=4)
    const int m_base = (wid >> 2) * 32;
    const int n_base = (wid & 3) * 32;

    float acc[2][4][4];
#pragma unroll
    for (int mt = 0; mt < 2; ++mt)
#pragma unroll
        for (int nt = 0; nt < 4; ++nt)
#pragma unroll
            for (int c = 0; c < 4; ++c) acc[mt][nt][c] = 0.f;

    // ---- prefetch chunk c_lo ----
    int4 ia = make_int4(0, 0, 0, 0), ib = make_int4(0, 0, 0, 0);
    uint4 xa, xb_;
    {
        int g0 = c_lo * 8 + dq_g;
        if (g0 < G_DIM) { ia = ibase[g0 >> 1]; ib = ibase[(g0 >> 1) + 1]; }
        xa  = xp[c_lo * 8 + xs * 2];
        xb_ = xp[c_lo * 8 + xs * 2 + 1];
    }

    for (int i = c_lo; i < c_hi; ++i) {
        // ---- prefetch chunk i+1 ----
        int4 na = make_int4(0, 0, 0, 0), nb = make_int4(0, 0, 0, 0);
        uint4 nxa = make_uint4(0, 0, 0, 0), nxb = make_uint4(0, 0, 0, 0);
        if (i + 1 < c_hi) {
            int g0 = (i + 1) * 8 + dq_g;
            if (g0 < G_DIM) { na = ibase[g0 >> 1]; nb = ibase[(g0 >> 1) + 1]; }
            nxa = xp[(i + 1) * 8 + xs * 2];
            nxb = xp[(i + 1) * 8 + xs * 2 + 1];
        }

        // ---- dequant 4 groups into s_w; stage x into s_x ----
        {
            const bool valid = (i * 8 + dq_g) < G_DIM;
            int id[8] = { ia.x, ia.y, ia.z, ia.w, ib.x, ib.y, ib.z, ib.w };
#pragma unroll
            for (int gi = 0; gi < 4; ++gi) {
                uint4 w;
                if (valid) {
                    uint4 e0 = s_cb[id[2 * gi] & 255];
                    uint4 e1 = s_cb[256 + (id[2 * gi + 1] & 255)];
                    w.x = hadd2u(e0.x, e1.x);
                    w.y = hadd2u(e0.y, e1.y);
                    w.z = hadd2u(e0.z, e1.z);
                    w.w = hadd2u(e0.w, e1.w);
                } else {
                    w = make_uint4(0, 0, 0, 0);
                }
                *reinterpret_cast<uint4*>(&s_w[dq_row][(dq_g + gi) * 8]) = w;
            }
            *reinterpret_cast<uint4*>(&s_x[xr][xs * 16])     = xa;
            *reinterpret_cast<uint4*>(&s_x[xr][xs * 16 + 8]) = xb_;
        }
        __syncthreads();

        // ---- MMA over chunk (k=64 -> 4 x k16), verified direct-LDS fragments ----
#pragma unroll
        for (int kk = 0; kk < 4; ++kk) {
            const int ac = kk * 16 + (lane & 3) * 2;
            uint32_t a[2][4];
#pragma unroll
            for (int mt = 0; mt < 2; ++mt) {
                const int ar = m_base + mt * 16 + (lane >> 2);
                a[mt][0] = *reinterpret_cast<const uint32_t*>(&s_x[ar][ac]);
                a[mt][1] = *reinterpret_cast<const uint32_t*>(&s_x[ar + 8][ac]);
                a[mt][2] = *reinterpret_cast<const uint32_t*>(&s_x[ar][ac + 8]);
                a[mt][3] = *reinterpret_cast<const uint32_t*>(&s_x[ar + 8][ac + 8]);
            }
#pragma unroll
            for (int nt = 0; nt < 4; ++nt) {
                const int br = n_base + nt * 8 + (lane >> 2);
                uint32_t b0 = *reinterpret_cast<const uint32_t*>(&s_w[br][ac]);
                uint32_t b1 = *reinterpret_cast<const uint32_t*>(&s_w[br][ac + 8]);
#pragma unroll
                for (int mt = 0; mt < 2; ++mt) {
                    asm volatile("mma.sync.aligned.m16n8k16.row.col.f32.f16.f16.f32 "
                                 "{%0,%1,%2,%3}, {%4,%5,%6,%7}, {%8,%9}, {%0,%1,%2,%3};"
                                 : "+f"(acc[mt][nt][0]), "+f"(acc[mt][nt][1]),
                                   "+f"(acc[mt][nt][2]), "+f"(acc[mt][nt][3])
                                 : "r"(a[mt][0]), "r"(a[mt][1]), "r"(a[mt][2]), "r"(a[mt][3]),
                                   "r"(b0), "r"(b1));
                }
            }
        }
        __syncthreads();

        ia = na; ib = nb; xa = nxa; xb_ = nxb;
    }

    // ---- write unscaled partials (deterministic, no atomics) ----
    float* part = &g_part[split][0];
#pragma unroll
    for (int mt = 0; mt < 2; ++mt) {
        const int t0 = m_base + mt * 16 + (lane >> 2);
#pragma unroll
        for (int nt = 0; nt < 4; ++nt) {
            const int o = o_base + n_base + nt * 8 + (lane & 3) * 2;
            *reinterpret_cast<float2*>(part + (size_t)t0 * OUT_DIM + o)
                = make_float2(acc[mt][nt][0], acc[mt][nt][1]);
            *reinterpret_cast<float2*>(part + (size_t)(t0 + 8) * OUT_DIM + o)
                = make_float2(acc[mt][nt][2], acc[mt][nt][3]);
        }
    }
}

// ---------- finalize: sum splits, scale, nan_to_num ----------
__global__ void k_final(const float* __restrict__ scales, float* __restrict__ out) {
    int idx = blockIdx.x * blockDim.x + threadIdx.x;   // over T*OUT/2 float2s
    if (idx >= T_DIM * OUT_DIM / 2) return;
    const int lin = idx * 2;
    const int o = lin % OUT_DIM;
    const size_t off = (size_t)lin;
    const float fac = g_xm * g_cbm;
    float2 p0 = *reinterpret_cast<const float2*>(&g_part[0][off]);
    float2 p1 = *reinterpret_cast<const float2*>(&g_part[1][off]);
    float2 p2 = *reinterpret_cast<const float2*>(&g_part[2][off]);
    float2 sc = *reinterpret_cast<const float2*>(&scales[o]);
    float v0 = finite_or_zero((p0.x + p1.x + p2.x) * sc.x * fac);
    float v1 = finite_or_zero((p0.y + p1.y + p2.y) * sc.y * fac);
    *reinterpret_cast<float2*>(&out[off]) = make_float2(v0, v1);
}

extern "C" void kernel_launch(void* const* d_in, const int* in_sizes, int n_in,
                              void* d_out, int out_size) {
    const float* x = nullptr;
    const int* indices = nullptr;
    const unsigned short* cbooks = nullptr;
    const float* scales = nullptr;
    for (int i = 0; i < n_in; ++i) {
        switch (in_sizes[i]) {
            case N_X:   x       = (const float*)d_in[i];          break;
            case N_IDX: indices = (const int*)d_in[i];            break;
            case N_CB:  cbooks  = (const unsigned short*)d_in[i]; break;
            case N_SC:  scales  = (const float*)d_in[i];          break;
            default: break;
        }
    }
    if (!x)       x       = (const float*)d_in[0];
    if (!indices) indices = (const int*)d_in[1];
    if (!cbooks)  cbooks  = (const unsigned short*)d_in[2];
    if (!scales)  scales  = (const float*)d_in[3];
    float* out = (float*)d_out;

    k_init<<<1, 1>>>();
    k_scan<<<64, 256>>>(x, cbooks);
    k_resolve<<<1, 32>>>(cbooks);
    k_xpad<<<(T_DIM * KP + 255) / 256, 256>>>(x);
    k_fused<<<NCTA, 256>>>(indices, cbooks);
    k_final<<<(T_DIM * OUT_DIM / 2 + 255) / 256, 256>>>(scales, out);
}

// round 14
// speedup vs baseline: 2.1361x; 1.1716x over previous
#include <cuda_runtime.h>
#include <cuda_fp16.h>
#include <cstdint>

#define T_DIM   64
#define IN_DIM  4100
#define OUT_DIM 12288
#define G_DIM   820
#define GPAD    824
#define KP      6592          // 824 groups * 8
#define NCHUNK  103           // KP / 64
#define O_TILE  128
#define NOTILE  96            // OUT_DIM / O_TILE
#define SPLITS  3
#define NCTA    (NOTILE * SPLITS)
#define LDSW    72            // smem row stride in halves (144B) -> conflict-free

#define N_X   (T_DIM * IN_DIM)        // 262400
#define N_IDX (OUT_DIM * G_DIM * 2)   // 20152320
#define N_CB  2560
#define N_SC  (OUT_DIM)               // 12288

__device__ unsigned g_xmax_bits, g_m16_bits, g_mb16_bits, g_m32_bits;
__device__ int   g_interp;    // 0=f16, 1=bf16, 2=f32
__device__ float g_cbm, g_xm;
__device__ __align__(16) __half g_xpad[T_DIM * KP];
__device__ __align__(16) float  g_part[SPLITS][(size_t)T_DIM * OUT_DIM];  // 9.4 MB

static __device__ __forceinline__ uint32_t s2u(const void* p) {
    uint32_t a;
    asm("{ .reg .u64 t; cvta.to.shared.u64 t, %1; cvt.u32.u64 %0, t; }" : "=r"(a) : "l"(p));
    return a;
}
static __device__ __forceinline__ uint32_t hadd2u(uint32_t a, uint32_t b) {
    __half2 ha = *reinterpret_cast<__half2*>(&a);
    __half2 hb = *reinterpret_cast<__half2*>(&b);
    __half2 r  = __hadd2(ha, hb);
    return *reinterpret_cast<uint32_t*>(&r);
}
static __device__ __forceinline__ float f16v(unsigned short u) {
    return __half2float(__ushort_as_half(u));
}
static __device__ __forceinline__ float bf16v(unsigned short u) {
    return __uint_as_float(((unsigned)u) << 16);
}
static __device__ __forceinline__ float finite_or_zero(float v) {
    unsigned u = __float_as_uint(v);
    return ((u & 0x7f800000u) == 0x7f800000u) ? 0.f : v;
}

// ---------- kernel: reset ----------
__global__ void k_init() {
    g_xmax_bits = 0u; g_m16_bits = 0u; g_mb16_bits = 0u; g_m32_bits = 0u;
}

// ---------- kernel: abs-max scans (verified) ----------
__global__ void k_scan(const float* __restrict__ x, const unsigned short* __restrict__ cb) {
    float mx = 0.f, mf = 0.f, mb = 0.f, m3 = 0.f;
    int stride = gridDim.x * blockDim.x;
    int t0 = blockIdx.x * blockDim.x + threadIdx.x;
    for (int i = t0; i < N_X; i += stride) mx = fmaxf(mx, fabsf(x[i]));
    for (int i = t0; i < N_CB; i += stride) {
        unsigned short u = cb[i];
        mf = fmaxf(mf, fabsf(f16v(u)));
        mb = fmaxf(mb, fabsf(bf16v(u)));
    }
    for (int i = t0; i < N_CB / 2; i += stride) {
        unsigned lo = cb[2 * i], hi = cb[2 * i + 1];
        m3 = fmaxf(m3, fabsf(__uint_as_float(lo | (hi << 16))));
    }
#pragma unroll
    for (int o = 16; o; o >>= 1) {
        mx = fmaxf(mx, __shfl_xor_sync(0xffffffffu, mx, o));
        mf = fmaxf(mf, __shfl_xor_sync(0xffffffffu, mf, o));
        mb = fmaxf(mb, __shfl_xor_sync(0xffffffffu, mb, o));
        m3 = fmaxf(m3, __shfl_xor_sync(0xffffffffu, m3, o));
    }
    if ((threadIdx.x & 31) == 0) {
        atomicMax(&g_xmax_bits, __float_as_uint(mx));
        atomicMax(&g_m16_bits,  __float_as_uint(mf));
        atomicMax(&g_mb16_bits, __float_as_uint(mb));
        atomicMax(&g_m32_bits,  __float_as_uint(m3));
    }
}

// ---------- kernel: resolve dtype + scalars (verified) ----------
__global__ void k_resolve(const unsigned short* __restrict__ cb) {
    int lane = threadIdx.x;
    float mf = __uint_as_float(g_m16_bits);
    float mb = __uint_as_float(g_mb16_bits);
    float m3 = __uint_as_float(g_m32_bits);
    int interp; float cbm;
    if      (mf >= 0.02f && mf <= 0.75f) { interp = 0; cbm = mf; }
    else if (mb >= 0.02f && mb <= 0.75f) { interp = 1; cbm = mb; }
    else if (m3 >= 0.02f && m3 <= 0.75f) { interp = 2; cbm = m3; }
    else                                  { interp = 1; cbm = mb; }
    if (interp == 2) {
        const float* f = (const float*)cb;
        float m = 0.f;
        for (int i = lane; i < N_CB; i += 32) m = fmaxf(m, fabsf(f[i]));
#pragma unroll
        for (int o = 16; o; o >>= 1) m = fmaxf(m, __shfl_xor_sync(0xffffffffu, m, o));
        cbm = m;
    }
    if (lane == 0) {
        g_interp = interp;
        g_cbm = fmaxf(cbm, 1.0f);
        g_xm  = fmaxf(__uint_as_float(g_xmax_bits), 1.0f) * 8.0f;
    }
}

// ---------- kernel: build padded fp16 x, one group (8 halves) per thread ----------
__global__ void k_xpad(const float* __restrict__ x) {
    int idx = blockIdx.x * blockDim.x + threadIdx.x;   // over T_DIM * GPAD groups
    if (idx >= T_DIM * GPAD) return;
    const float inv = 1.0f / g_xm;
    int t = idx / GPAD;
    int g = idx - t * GPAD;
    union { uint4 v4; __half h[8]; } u;
    if (g < G_DIM) {
        const float* xp = x + (size_t)t * IN_DIM + g * 5;
#pragma unroll
        for (int j = 0; j < 5; ++j) u.h[j] = __float2half(xp[j] * inv);
        u.h[5] = u.h[6] = u.h[7] = __ushort_as_half((unsigned short)0);
    } else {
        u.v4 = make_uint4(0, 0, 0, 0);
    }
    *reinterpret_cast<uint4*>(g_xpad + (size_t)t * KP + g * 8) = u.v4;
}

// ---------- fused dequant + GEMM (R10-verified; fragments now via ldmatrix) ----------
__global__ void __launch_bounds__(256, 2)
k_fused(const int* __restrict__ indices, const unsigned short* __restrict__ cb) {
    __shared__ __align__(16) uint4  s_cb[512];            // 8 KB
    __shared__ __align__(16) __half s_w[O_TILE][LDSW];    // 18 KB
    __shared__ __align__(16) __half s_x[T_DIM][LDSW];     // 9 KB

    const int tid  = threadIdx.x;
    const int lane = tid & 31;
    const int wid  = tid >> 5;
    const int o_tile = blockIdx.x % NOTILE;
    const int split  = blockIdx.x / NOTILE;
    const int o_base = o_tile * O_TILE;
    const int c_lo = (split == 0) ? 0  : (split == 1 ? 35 : 69);
    const int c_hi = (split == 0) ? 35 : (split == 1 ? 69 : 103);

    // ---- build normalized padded codebook in smem (verified) ----
    {
        const int interp = g_interp;
        const float cbm = g_cbm;
        for (int e = tid; e < 512; e += 256) {
            union { uint4 v4; __half h[8]; } u;
#pragma unroll
            for (int j = 0; j < 8; ++j) {
                float v = 0.f;
                if (j < 5) {
                    int k = e * 5 + j;
                    if      (interp == 0) v = f16v(cb[k]);
                    else if (interp == 1) v = bf16v(cb[k]);
                    else                  v = ((const float*)cb)[k];
                }
                u.h[j] = __float2half(v / cbm);
            }
            s_cb[e] = u.v4;
        }
    }
    __syncthreads();

    // ---- dequant / staging assignments (verified R10) ----
    const int dq_row = tid >> 1;            // 0..127: W tile row
    const int dq_g   = (tid & 1) * 4;       // group segment within chunk (0 or 4)
    const int4* ibase = (const int4*)indices + (size_t)(o_base + dq_row) * (G_DIM / 2);
    const int xr = tid >> 2;                // 0..63: x tile row
    const int xs = tid & 3;                 // 16-half segment
    const uint4* xp = (const uint4*)(g_xpad + (size_t)xr * KP);

    // warp tiling: m32 x n32 per warp (Wm=2, Wn=4)
    const int m_base = (wid >> 2) * 32;
    const int n_base = (wid & 3) * 32;

    // precomputed ldmatrix lane addresses (byte offsets into s_x / s_w)
    const uint32_t sxb = s2u(&s_x[0][0]);
    const uint32_t swb = s2u(&s_w[0][0]);
    // A.x4: row = m_base + mt*16 + (lane&15), col(half) = kk*16 + (lane>>4)*8
    const uint32_t a_row_off = (uint32_t)(m_base + (lane & 15)) * (LDSW * 2);
    const uint32_t a_col_off = (uint32_t)((lane >> 4) * 8) * 2;
    // B.x4 (covers nt, nt+1): row = n_base + nt*8 + (lane&7) + ((lane>>4)&1)*8,
    //                         col(half) = kk*16 + ((lane>>3)&1)*8
    const uint32_t b_row_off = (uint32_t)(n_base + (lane & 7) + ((lane >> 4) & 1) * 8) * (LDSW * 2);
    const uint32_t b_col_off = (uint32_t)(((lane >> 3) & 1) * 8) * 2;

    float acc[2][4][4];
#pragma unroll
    for (int mt = 0; mt < 2; ++mt)
#pragma unroll
        for (int nt = 0; nt < 4; ++nt)
#pragma unroll
            for (int c = 0; c < 4; ++c) acc[mt][nt][c] = 0.f;

    // ---- prefetch chunk c_lo ----
    int4 ia = make_int4(0, 0, 0, 0), ib = make_int4(0, 0, 0, 0);
    uint4 xa, xb_;
    {
        int g0 = c_lo * 8 + dq_g;
        if (g0 < G_DIM) { ia = ibase[g0 >> 1]; ib = ibase[(g0 >> 1) + 1]; }
        xa  = xp[c_lo * 8 + xs * 2];
        xb_ = xp[c_lo * 8 + xs * 2 + 1];
    }

    for (int i = c_lo; i < c_hi; ++i) {
        // ---- prefetch chunk i+1 ----
        int4 na = make_int4(0, 0, 0, 0), nb = make_int4(0, 0, 0, 0);
        uint4 nxa = make_uint4(0, 0, 0, 0), nxb = make_uint4(0, 0, 0, 0);
        if (i + 1 < c_hi) {
            int g0 = (i + 1) * 8 + dq_g;
            if (g0 < G_DIM) { na = ibase[g0 >> 1]; nb = ibase[(g0 >> 1) + 1]; }
            nxa = xp[(i + 1) * 8 + xs * 2];
            nxb = xp[(i + 1) * 8 + xs * 2 + 1];
        }

        // ---- dequant 4 groups into s_w; stage x into s_x (verified R10) ----
        {
            const bool valid = (i * 8 + dq_g) < G_DIM;
            int id[8] = { ia.x, ia.y, ia.z, ia.w, ib.x, ib.y, ib.z, ib.w };
#pragma unroll
            for (int gi = 0; gi < 4; ++gi) {
                uint4 w;
                if (valid) {
                    uint4 e0 = s_cb[id[2 * gi] & 255];
                    uint4 e1 = s_cb[256 + (id[2 * gi + 1] & 255)];
                    w.x = hadd2u(e0.x, e1.x);
                    w.y = hadd2u(e0.y, e1.y);
                    w.z = hadd2u(e0.z, e1.z);
                    w.w = hadd2u(e0.w, e1.w);
                } else {
                    w = make_uint4(0, 0, 0, 0);
                }
                *reinterpret_cast<uint4*>(&s_w[dq_row][(dq_g + gi) * 8]) = w;
            }
            *reinterpret_cast<uint4*>(&s_x[xr][xs * 16])     = xa;
            *reinterpret_cast<uint4*>(&s_x[xr][xs * 16 + 8]) = xb_;
        }
        __syncthreads();

        // ---- MMA over chunk (k=64 -> 4 x k16), fragments via ldmatrix ----
#pragma unroll
        for (int kk = 0; kk < 4; ++kk) {
            const uint32_t kbase = (uint32_t)(kk * 16) * 2;
            uint32_t a[2][4];
#pragma unroll
            for (int mt = 0; mt < 2; ++mt) {
                uint32_t aaddr = sxb + a_row_off + (uint32_t)(mt * 16) * (LDSW * 2)
                               + kbase + a_col_off;
                asm volatile("ldmatrix.sync.aligned.m8n8.x4.shared.b16 {%0,%1,%2,%3}, [%4];"
                             : "=r"(a[mt][0]), "=r"(a[mt][1]), "=r"(a[mt][2]), "=r"(a[mt][3])
                             : "r"(aaddr));
            }
#pragma unroll
            for (int np = 0; np < 2; ++np) {       // nt pair: (2*np, 2*np+1)
                uint32_t b0, b1, b2, b3;
                uint32_t baddr = swb + b_row_off + (uint32_t)(np * 16) * (LDSW * 2)
                               + kbase + b_col_off;
                asm volatile("ldmatrix.sync.aligned.m8n8.x4.shared.b16 {%0,%1,%2,%3}, [%4];"
                             : "=r"(b0), "=r"(b1), "=r"(b2), "=r"(b3) : "r"(baddr));
#pragma unroll
                for (int mt = 0; mt < 2; ++mt) {
                    asm volatile("mma.sync.aligned.m16n8k16.row.col.f32.f16.f16.f32 "
                                 "{%0,%1,%2,%3}, {%4,%5,%6,%7}, {%8,%9}, {%0,%1,%2,%3};"
                                 : "+f"(acc[mt][2 * np][0]), "+f"(acc[mt][2 * np][1]),
                                   "+f"(acc[mt][2 * np][2]), "+f"(acc[mt][2 * np][3])
                                 : "r"(a[mt][0]), "r"(a[mt][1]), "r"(a[mt][2]), "r"(a[mt][3]),
                                   "r"(b0), "r"(b1));
                    asm volatile("mma.sync.aligned.m16n8k16.row.col.f32.f16.f16.f32 "
                                 "{%0,%1,%2,%3}, {%4,%5,%6,%7}, {%8,%9}, {%0,%1,%2,%3};"
                                 : "+f"(acc[mt][2 * np + 1][0]), "+f"(acc[mt][2 * np + 1][1]),
                                   "+f"(acc[mt][2 * np + 1][2]), "+f"(acc[mt][2 * np + 1][3])
                                 : "r"(a[mt][0]), "r"(a[mt][1]), "r"(a[mt][2]), "r"(a[mt][3]),
                                   "r"(b2), "r"(b3));
                }
            }
        }
        __syncthreads();

        ia = na; ib = nb; xa = nxa; xb_ = nxb;
    }

    // ---- write unscaled partials (verified R10) ----
    float* part = &g_part[split][0];
#pragma unroll
    for (int mt = 0; mt < 2; ++mt) {
        const int t0 = m_base + mt * 16 + (lane >> 2);
#pragma unroll
        for (int nt = 0; nt < 4; ++nt) {
            const int o = o_base + n_base + nt * 8 + (lane & 3) * 2;
            *reinterpret_cast<float2*>(part + (size_t)t0 * OUT_DIM + o)
                = make_float2(acc[mt][nt][0], acc[mt][nt][1]);
            *reinterpret_cast<float2*>(part + (size_t)(t0 + 8) * OUT_DIM + o)
                = make_float2(acc[mt][nt][2], acc[mt][nt][3]);
        }
    }
}

// ---------- finalize: sum splits, scale, nan_to_num (verified) ----------
__global__ void k_final(const float* __restrict__ scales, float* __restrict__ out) {
    int idx = blockIdx.x * blockDim.x + threadIdx.x;
    if (idx >= T_DIM * OUT_DIM / 2) return;
    const int lin = idx * 2;
    const int o = lin % OUT_DIM;
    const size_t off = (size_t)lin;
    const float fac = g_xm * g_cbm;
    float2 p0 = *reinterpret_cast<const float2*>(&g_part[0][off]);
    float2 p1 = *reinterpret_cast<const float2*>(&g_part[1][off]);
    float2 p2 = *reinterpret_cast<const float2*>(&g_part[2][off]);
    float2 sc = *reinterpret_cast<const float2*>(&scales[o]);
    float v0 = finite_or_zero((p0.x + p1.x + p2.x) * sc.x * fac);
    float v1 = finite_or_zero((p0.y + p1.y + p2.y) * sc.y * fac);
    *reinterpret_cast<float2*>(&out[off]) = make_float2(v0, v1);
}

extern "C" void kernel_launch(void* const* d_in, const int* in_sizes, int n_in,
                              void* d_out, int out_size) {
    const float* x = nullptr;
    const int* indices = nullptr;
    const unsigned short* cbooks = nullptr;
    const float* scales = nullptr;
    for (int i = 0; i < n_in; ++i) {
        switch (in_sizes[i]) {
            case N_X:   x       = (const float*)d_in[i];          break;
            case N_IDX: indices = (const int*)d_in[i];            break;
            case N_CB:  cbooks  = (const unsigned short*)d_in[i]; break;
            case N_SC:  scales  = (const float*)d_in[i];          break;
            default: break;
        }
    }
    if (!x)       x       = (const float*)d_in[0];
    if (!indices) indices = (const int*)d_in[1];
    if (!cbooks)  cbooks  = (const unsigned short*)d_in[2];
    if (!scales)  scales  = (const float*)d_in[3];
    float* out = (float*)d_out;

    k_init<<<1, 1>>>();
    k_scan<<<64, 256>>>(x, cbooks);
    k_resolve<<<1, 32>>>(cbooks);
    k_xpad<<<(T_DIM * GPAD + 255) / 256, 256>>>(x);
    k_fused<<<NCTA, 256>>>(indices, cbooks);
    k_final<<<(T_DIM * OUT_DIM / 2 + 255) / 256, 256>>>(scales, out);
}